// round 6
// baseline (speedup 1.0000x reference)
#include <cuda_runtime.h>
#include <cuda_bf16.h>
#include <math.h>

// ---------------------------------------------------------------------------
// MegatronAttention B=2,S=2048,H=2048,NH=16,DH=128 — mma.sync bf16x3-split GEMMs
// CTA tile 128x256, warp tile 64x64, KC=64, 2-stage cp.async pipeline,
// all problem constants templated (register diet vs R4's 255-reg spill).
// out quirk: einsum 'bhqk,bhkd->bhkd' sums q -> out = v * colsum(softmax).
// ---------------------------------------------------------------------------
#define SEQ 2048
#define HDIM 2048
#define NH 16
#define DHEAD 128
#define MR 4096               // B*S
#define QN 6144               // 3*NH*DH
#define NBH 32
#define NTILES 32             // 2048/64 score col-tiles per row

typedef long long ll;
typedef unsigned int u32;

// --------------------------- scratch buffers -------------------------------
__device__ __nv_bfloat16 g_xhi[(size_t)MR*HDIM], g_xlo[(size_t)MR*HDIM];
__device__ __nv_bfloat16 g_wqT_hi[(size_t)QN*HDIM], g_wqT_lo[(size_t)QN*HDIM];
__device__ __nv_bfloat16 g_woT_hi[(size_t)HDIM*HDIM], g_woT_lo[(size_t)HDIM*HDIM];
__device__ __nv_bfloat16 g_qkv_hi[(size_t)MR*QN], g_qkv_lo[(size_t)MR*QN];
__device__ float g_scores[(size_t)NBH*SEQ*SEQ];
__device__ __nv_bfloat16 g_vhi[(size_t)MR*HDIM], g_vlo[(size_t)MR*HDIM];
__device__ float g_pmax[(size_t)NBH*SEQ*NTILES], g_psum[(size_t)NBH*SEQ*NTILES];
__device__ float g_rowmax[NBH*SEQ], g_rowinv[NBH*SEQ], g_colsum[NBH*SEQ];

// --------------------------- helpers ---------------------------------------
__device__ __forceinline__ u32 s2u(const void* p){
    u32 a; asm("{ .reg .u64 t; cvta.to.shared.u64 t, %1; cvt.u32.u64 %0, t; }":"=r"(a):"l"(p)); return a;
}
#define SWZ(o) ((o) ^ (((o)>>3)&0x70))

__device__ __forceinline__ void cpa16(u32 d, const void* s){
    asm volatile("cp.async.cg.shared.global [%0], [%1], 16;" :: "r"(d), "l"(s));
}
__device__ __forceinline__ void cpc(){ asm volatile("cp.async.commit_group;"); }
template<int N> __device__ __forceinline__ void cpw(){ asm volatile("cp.async.wait_group %0;"::"n"(N)); }

__device__ __forceinline__ void ldm4(u32* r, u32 addr){
    asm volatile("ldmatrix.sync.aligned.m8n8.x4.shared.b16 {%0,%1,%2,%3}, [%4];"
        : "=r"(r[0]),"=r"(r[1]),"=r"(r[2]),"=r"(r[3]) : "r"(addr));
}
__device__ __forceinline__ void mma16816(float* d, const u32* a, u32 b0, u32 b1){
    asm volatile("mma.sync.aligned.m16n8k16.row.col.f32.bf16.bf16.f32 "
        "{%0,%1,%2,%3}, {%4,%5,%6,%7}, {%8,%9}, {%0,%1,%2,%3};"
        : "+f"(d[0]),"+f"(d[1]),"+f"(d[2]),"+f"(d[3])
        : "r"(a[0]),"r"(a[1]),"r"(a[2]),"r"(a[3]), "r"(b0),"r"(b1));
}
__device__ __forceinline__ void bsplit(float v, __nv_bfloat16& h, __nv_bfloat16& l){
    h = __float2bfloat16(v);
    l = __float2bfloat16(v - __bfloat162float(h));
}

// --------------------------- mma.sync GEMM ---------------------------------
// C[M,N] = alpha * sum_k A[m,k]*B[n,k] (row-major, k contiguous; "NT").
// A/B pre-split bf16 hi/lo; 3-term product.
#define KC 64
#define A_TILE 16384              // 128 x 128B
#define B_TILE 32768              // 256 x 128B
#define STAGE_BYTES (2*A_TILE + 2*B_TILE)   // 96KB
#define GSMEM_SZ (1024 + 2*STAGE_BYTES)

// EPI: 0 = f32 out, 1 = split bf16 hi/lo out, 2 = f32 scores + partial softmax
template<int EPI, int K, int LDA, int LDB, int LDC, int ZDIV,
         ll SAO, ll SAI, ll SBO, ll SBI, ll SCO, ll SCI>
__global__ __launch_bounds__(256, 1)
void gemm_mma(const __nv_bfloat16* __restrict__ Ahi, const __nv_bfloat16* __restrict__ Alo,
              const __nv_bfloat16* __restrict__ Bhi, const __nv_bfloat16* __restrict__ Blo,
              float* __restrict__ Cf, __nv_bfloat16* __restrict__ Chi, __nv_bfloat16* __restrict__ Clo,
              float* __restrict__ Pm, float* __restrict__ Ps, float alpha)
{
    extern __shared__ char smem[];
    const u32 stage0 = (s2u(smem) + 1023u) & ~1023u;
    const int tid = threadIdx.x;
    const int lane = tid & 31;
    const int wid = tid >> 5;
    const int wm = (wid & 1) * 64;
    const int wn = (wid >> 1) * 64;
    const int lrow16 = lane & 15;
    const int lcol16 = (lane >> 4) * 16;

    const int zo = blockIdx.z / ZDIV, zi = blockIdx.z % ZDIV;
    const ll aoff = zo*SAO + zi*SAI;
    const ll boff = zo*SBO + zi*SBI;
    const ll coff = zo*SCO + zi*SCI;

    const int m0 = blockIdx.y * 128;
    const int n0 = blockIdx.x * 256;
    const int NK = K / KC;

    // loader: A 2 thr/row (4x16B each), B 1 thr/row (8x16B)
    const int arow = tid >> 1;
    const int aseg0 = (tid & 1) * 4;
    const __nv_bfloat16* pAh = Ahi + aoff + (ll)(m0 + arow)*LDA + aseg0*8;
    const __nv_bfloat16* pAl = Alo + aoff + (ll)(m0 + arow)*LDA + aseg0*8;
    const __nv_bfloat16* pBh = Bhi + boff + (ll)(n0 + tid)*LDB;
    const __nv_bfloat16* pBl = Blo + boff + (ll)(n0 + tid)*LDB;
    u32 adst[4], bdst[8];
    #pragma unroll
    for (int j = 0; j < 4; j++) adst[j] = SWZ((u32)(arow*128 + (aseg0 + j)*16));
    #pragma unroll
    for (int j = 0; j < 8; j++) bdst[j] = SWZ((u32)(tid*128 + j*16));

    auto fetch = [&](u32 sbit){
        const u32 base = stage0 + sbit * STAGE_BYTES;
        #pragma unroll
        for (int j = 0; j < 4; j++) cpa16(base + adst[j],            pAh + j*8);
        #pragma unroll
        for (int j = 0; j < 4; j++) cpa16(base + A_TILE + bdst[0]*0 + adst[j], pAl + j*8);
        #pragma unroll
        for (int j = 0; j < 8; j++) cpa16(base + 2*A_TILE + bdst[j], pBh + j*8);
        #pragma unroll
        for (int j = 0; j < 8; j++) cpa16(base + 2*A_TILE + B_TILE + bdst[j], pBl + j*8);
        cpc();
        pAh += KC; pAl += KC; pBh += KC; pBl += KC;
    };

    float acc[4][8][4];
    #pragma unroll
    for (int i=0;i<4;i++)
    #pragma unroll
    for (int j=0;j<8;j++)
    #pragma unroll
    for (int r=0;r<4;r++) acc[i][j][r] = 0.f;

    fetch(0);
    for (int kc = 0; kc < NK; kc++) {
        if (kc + 1 < NK) { fetch((kc+1) & 1); cpw<1>(); } else { cpw<0>(); }
        __syncthreads();

        const u32 sb  = stage0 + (kc & 1) * STAGE_BYTES;
        const u32 sAh = sb, sAl = sb + A_TILE;
        const u32 sBh = sb + 2*A_TILE, sBl = sb + 2*A_TILE + B_TILE;

        #pragma unroll
        for (int k16 = 0; k16 < 4; k16++) {
            u32 ah[4][4], al[4][4];
            #pragma unroll
            for (int mf = 0; mf < 4; mf++) {
                u32 off = SWZ((u32)((wm + mf*16 + lrow16)*128 + k16*32 + lcol16));
                ldm4(ah[mf], sAh + off);
                ldm4(al[mf], sAl + off);
            }
            #pragma unroll
            for (int n2 = 0; n2 < 4; n2++) {
                u32 bh[4], bl[4];
                u32 off = SWZ((u32)((wn + n2*16 + lrow16)*128 + k16*32 + lcol16));
                ldm4(bh, sBh + off);
                ldm4(bl, sBl + off);
                #pragma unroll
                for (int od = 0; od < 2; od++) {
                    const int nf = n2*2 + od;
                    #pragma unroll
                    for (int mf = 0; mf < 4; mf++) {
                        mma16816(acc[mf][nf], ah[mf], bh[od], bh[od+2]);
                        mma16816(acc[mf][nf], ah[mf], bl[od], bl[od+2]);
                        mma16816(acc[mf][nf], al[mf], bh[od], bh[od+2]);
                    }
                }
            }
        }
        __syncthreads();
    }

    const int g = lane >> 2, tig = lane & 3;
    #pragma unroll
    for (int mf = 0; mf < 4; mf++) {
        #pragma unroll
        for (int nf = 0; nf < 8; nf++) {
            const ll m = m0 + wm + mf*16 + g;
            const int n = n0 + wn + nf*8 + tig*2;
            float d0 = acc[mf][nf][0]*alpha, d1 = acc[mf][nf][1]*alpha;
            float d2 = acc[mf][nf][2]*alpha, d3 = acc[mf][nf][3]*alpha;
            if (EPI != 1) {
                float2 v01 = {d0, d1}, v23 = {d2, d3};
                *reinterpret_cast<float2*>(Cf + coff + m*LDC + n) = v01;
                *reinterpret_cast<float2*>(Cf + coff + (m+8)*LDC + n) = v23;
            } else {
                __nv_bfloat16 h0,l0,h1,l1,h2,l2,h3,l3;
                bsplit(d0,h0,l0); bsplit(d1,h1,l1); bsplit(d2,h2,l2); bsplit(d3,h3,l3);
                __nv_bfloat162 hh01; hh01.x=h0; hh01.y=h1;
                __nv_bfloat162 ll01; ll01.x=l0; ll01.y=l1;
                __nv_bfloat162 hh23; hh23.x=h2; hh23.y=h3;
                __nv_bfloat162 ll23; ll23.x=l2; ll23.y=l3;
                *reinterpret_cast<u32*>(Chi + coff + m*LDC + n) = *reinterpret_cast<u32*>(&hh01);
                *reinterpret_cast<u32*>(Clo + coff + m*LDC + n) = *reinterpret_cast<u32*>(&ll01);
                *reinterpret_cast<u32*>(Chi + coff + (m+8)*LDC + n) = *reinterpret_cast<u32*>(&hh23);
                *reinterpret_cast<u32*>(Clo + coff + (m+8)*LDC + n) = *reinterpret_cast<u32*>(&ll23);
            }
        }
    }

    if (EPI == 2) {
        // partial softmax stats over this warp's 64 cols (alpha already folded? no: fold here)
        const int bh = blockIdx.z;
        const int nt = (n0 + wn) >> 6;
        #pragma unroll
        for (int mf = 0; mf < 4; mf++) {
            #pragma unroll
            for (int half = 0; half < 2; half++) {
                const int r0i = half * 2;
                float mx = -1e30f;
                #pragma unroll
                for (int nf = 0; nf < 8; nf++)
                    mx = fmaxf(mx, fmaxf(acc[mf][nf][r0i], acc[mf][nf][r0i+1]));
                mx = fmaxf(mx, __shfl_xor_sync(0xffffffffu, mx, 1));
                mx = fmaxf(mx, __shfl_xor_sync(0xffffffffu, mx, 2));
                float sm = 0.f;
                #pragma unroll
                for (int nf = 0; nf < 8; nf++)
                    sm += __expf((acc[mf][nf][r0i] - mx)*alpha) + __expf((acc[mf][nf][r0i+1] - mx)*alpha);
                sm += __shfl_xor_sync(0xffffffffu, sm, 1);
                sm += __shfl_xor_sync(0xffffffffu, sm, 2);
                if (tig == 0) {
                    const int row = m0 + wm + mf*16 + g + half*8;
                    const ll idx = ((ll)bh*SEQ + row)*NTILES + nt;
                    Pm[idx] = mx*alpha; Ps[idx] = sm;
                }
            }
        }
    }
}

// --------------------------- prep kernels ----------------------------------
__global__ __launch_bounds__(256)
void split_x_kernel(const float* __restrict__ x, __nv_bfloat16* __restrict__ hi,
                    __nv_bfloat16* __restrict__ lo)
{
    const ll i = (ll)blockIdx.x * 256 + threadIdx.x;
    float v = x[i];
    __nv_bfloat16 h, l; bsplit(v, h, l);
    hi[i] = h; lo[i] = l;
}

// in [R,C] f32 -> out [C,R] split bf16
__global__ __launch_bounds__(256)
void transpose_split_kernel(const float* __restrict__ in, __nv_bfloat16* __restrict__ ohi,
                            __nv_bfloat16* __restrict__ olo, int R, int C)
{
    __shared__ float t[32][33];
    const int c0 = blockIdx.x * 32, r0 = blockIdx.y * 32;
    const int tx = threadIdx.x, ty = threadIdx.y;
    #pragma unroll
    for (int i = 0; i < 4; i++)
        t[ty + 8*i][tx] = in[(ll)(r0 + ty + 8*i) * C + c0 + tx];
    __syncthreads();
    #pragma unroll
    for (int i = 0; i < 4; i++) {
        float v = t[tx][ty + 8*i];
        __nv_bfloat16 h, l; bsplit(v, h, l);
        const ll o = (ll)(c0 + ty + 8*i) * R + r0 + tx;
        ohi[o] = h; olo[o] = l;
    }
}

// --------------------------- stats combine ---------------------------------
__global__ __launch_bounds__(256)
void stats_combine_kernel(const float* __restrict__ Pm, const float* __restrict__ Ps,
                          float* __restrict__ rowmax, float* __restrict__ rowinv)
{
    const int row = blockIdx.x * 8 + (threadIdx.x >> 5);
    const int lane = threadIdx.x & 31;
    float m = Pm[(ll)row*NTILES + lane];
    float s = Ps[(ll)row*NTILES + lane];
    float gm = m;
    #pragma unroll
    for (int o = 16; o; o >>= 1) gm = fmaxf(gm, __shfl_xor_sync(0xffffffffu, gm, o));
    float z = s * __expf(m - gm);
    #pragma unroll
    for (int o = 16; o; o >>= 1) z += __shfl_xor_sync(0xffffffffu, z, o);
    if (lane == 0) { rowmax[row] = gm; rowinv[row] = 1.0f / z; }
}

// colsum with q-split + atomics: grid (k_chunks, bh, q_chunks)
__global__ __launch_bounds__(256)
void colsum2_kernel(const float* __restrict__ S, const float* __restrict__ rowmax,
                    const float* __restrict__ rowinv, float* __restrict__ colsum)
{
    const int bh = blockIdx.y;
    const int k  = blockIdx.x * 256 + threadIdx.x;
    const int q0 = blockIdx.z * 128;
    const float* sp = S + (ll)bh*SEQ*SEQ + (ll)q0*SEQ + k;
    const float* mp = rowmax + bh*SEQ + q0;
    const float* ip = rowinv + bh*SEQ + q0;
    float acc = 0.f;
    #pragma unroll 4
    for (int q = 0; q < 128; q++)
        acc += __expf(sp[(ll)q*SEQ] - __ldg(&mp[q])) * __ldg(&ip[q]);
    atomicAdd(&colsum[bh*SEQ + k], acc);
}

// vals = v * colsum, re-split to bf16 hi/lo
__global__ __launch_bounds__(256)
void scale_v_split_kernel(const __nv_bfloat16* __restrict__ qhi, const __nv_bfloat16* __restrict__ qlo,
                          const float* __restrict__ colsum,
                          __nv_bfloat16* __restrict__ vhi, __nv_bfloat16* __restrict__ vlo)
{
    const ll idx = (ll)blockIdx.x * 256 + threadIdx.x;
    const int col = (int)(idx & (HDIM - 1));
    const int row = (int)(idx >> 11);
    const int h = col >> 7;
    const int b = row >> 11;
    const int s = row & (SEQ - 1);
    const ll qo = (ll)row * QN + 2*NH*DHEAD + col;
    float v = __bfloat162float(qhi[qo]) + __bfloat162float(qlo[qo]);
    v *= colsum[(b*NH + h)*SEQ + s];
    __nv_bfloat16 h16, l16; bsplit(v, h16, l16);
    vhi[idx] = h16; vlo[idx] = l16;
}

// ---------------------------------------------------------------------------
extern "C" void kernel_launch(void* const* d_in, const int* in_sizes, int n_in,
                              void* d_out, int out_size)
{
    const float* x     = (const float*)d_in[0];
    const float* w_qkv = (const float*)d_in[1];
    const float* w_o   = (const float*)d_in[2];
    float* out = (float*)d_out;

    __nv_bfloat16 *xhi,*xlo,*wqh,*wql,*woh,*wol,*qh,*qlp,*vh,*vl;
    float *scores,*rowmax,*rowinv,*colsum,*pmax,*psum;
    cudaGetSymbolAddress((void**)&xhi, g_xhi);   cudaGetSymbolAddress((void**)&xlo, g_xlo);
    cudaGetSymbolAddress((void**)&wqh, g_wqT_hi); cudaGetSymbolAddress((void**)&wql, g_wqT_lo);
    cudaGetSymbolAddress((void**)&woh, g_woT_hi); cudaGetSymbolAddress((void**)&wol, g_woT_lo);
    cudaGetSymbolAddress((void**)&qh,  g_qkv_hi); cudaGetSymbolAddress((void**)&qlp, g_qkv_lo);
    cudaGetSymbolAddress((void**)&vh,  g_vhi);    cudaGetSymbolAddress((void**)&vl,  g_vlo);
    cudaGetSymbolAddress((void**)&scores, g_scores);
    cudaGetSymbolAddress((void**)&rowmax, g_rowmax);
    cudaGetSymbolAddress((void**)&rowinv, g_rowinv);
    cudaGetSymbolAddress((void**)&colsum, g_colsum);
    cudaGetSymbolAddress((void**)&pmax, g_pmax);
    cudaGetSymbolAddress((void**)&psum, g_psum);

    // GEMM instantiations (all constants compile-time)
    auto k_qkv = gemm_mma<1, HDIM, HDIM, HDIM, QN, 1, 0,0,0,0,0,0>;
    auto k_sc  = gemm_mma<2, DHEAD, QN, QN, SEQ, NH,
                          (ll)SEQ*QN, 128, (ll)SEQ*QN, 128,
                          (ll)NH*SEQ*SEQ, (ll)SEQ*SEQ>;
    auto k_out = gemm_mma<0, HDIM, HDIM, HDIM, HDIM, 1, 0,0,0,0,0,0>;
    cudaFuncSetAttribute(k_qkv, cudaFuncAttributeMaxDynamicSharedMemorySize, GSMEM_SZ);
    cudaFuncSetAttribute(k_sc,  cudaFuncAttributeMaxDynamicSharedMemorySize, GSMEM_SZ);
    cudaFuncSetAttribute(k_out, cudaFuncAttributeMaxDynamicSharedMemorySize, GSMEM_SZ);

    // prep: split/transpose inputs
    split_x_kernel<<<(MR*HDIM)/256, 256>>>(x, xhi, xlo);
    transpose_split_kernel<<<dim3(QN/32, HDIM/32), dim3(32,8)>>>(w_qkv, wqh, wql, HDIM, QN);
    transpose_split_kernel<<<dim3(HDIM/32, HDIM/32), dim3(32,8)>>>(w_o, woh, wol, HDIM, HDIM);

    // 1) qkv = x @ w_qkv (split bf16 out)
    k_qkv<<<dim3(QN/256, MR/128, 1), 256, GSMEM_SZ>>>(
        xhi, xlo, wqh, wql, nullptr, qh, qlp, nullptr, nullptr, 1.0f);

    // 2) scores = (Q @ K^T)/sqrt(128) + partial softmax stats, z = b*16+h
    k_sc<<<dim3(SEQ/256, SEQ/128, NBH), 256, GSMEM_SZ>>>(
        qh, qlp, qh + NH*DHEAD, qlp + NH*DHEAD, scores, nullptr, nullptr,
        pmax, psum, 0.08838834764831845f);

    // 3) combine partial stats
    stats_combine_kernel<<<(NBH*SEQ)/8, 256>>>(pmax, psum, rowmax, rowinv);

    // 4) colsum over q (atomic, q-split)
    cudaMemsetAsync(colsum, 0, NBH*SEQ*sizeof(float));
    colsum2_kernel<<<dim3(SEQ/256, NBH, SEQ/128), 256>>>(scores, rowmax, rowinv, colsum);

    // 5) vals = v * colsum, split
    scale_v_split_kernel<<<(MR*HDIM)/256, 256>>>(qh, qlp, colsum, vh, vl);

    // 6) out = vals @ w_o
    k_out<<<dim3(HDIM/256, MR/128, 1), 256, GSMEM_SZ>>>(
        vh, vl, woh, wol, out, nullptr, nullptr, nullptr, nullptr, 1.0f);
}

// round 7
// speedup vs baseline: 1.2302x; 1.2302x over previous
#include <cuda_runtime.h>
#include <cuda_bf16.h>
#include <math.h>

// ---------------------------------------------------------------------------
// MegatronAttention B=2,S=2048,H=2048,NH=16,DH=128 — mma.sync bf16x3-split GEMMs
// CTA tile 128x128, warp tile 64x32, KC=32 (SW64), PIPE=3, 2 CTAs/SM.
// A-hi/A-lo two-pass fragment reuse keeps regs under the 128/2-CTA cap.
// out quirk: einsum 'bhqk,bhkd->bhkd' sums q -> out = v * colsum(softmax).
// ---------------------------------------------------------------------------
#define SEQ 2048
#define HDIM 2048
#define NH 16
#define DHEAD 128
#define MR 4096               // B*S
#define QN 6144               // 3*NH*DH
#define NBH 32
#define NTILES 64             // 2048/32 score col-tiles per row

typedef long long ll;
typedef unsigned int u32;

// --------------------------- scratch buffers -------------------------------
__device__ __nv_bfloat16 g_xhi[(size_t)MR*HDIM], g_xlo[(size_t)MR*HDIM];
__device__ __nv_bfloat16 g_wqT_hi[(size_t)QN*HDIM], g_wqT_lo[(size_t)QN*HDIM];
__device__ __nv_bfloat16 g_woT_hi[(size_t)HDIM*HDIM], g_woT_lo[(size_t)HDIM*HDIM];
__device__ __nv_bfloat16 g_qkv_hi[(size_t)MR*QN], g_qkv_lo[(size_t)MR*QN];
__device__ float g_scores[(size_t)NBH*SEQ*SEQ];
__device__ __nv_bfloat16 g_vhi[(size_t)MR*HDIM], g_vlo[(size_t)MR*HDIM];
__device__ float g_pmax[(size_t)NBH*SEQ*NTILES], g_psum[(size_t)NBH*SEQ*NTILES];
__device__ float g_rowmax[NBH*SEQ], g_rowinv[NBH*SEQ], g_colsum[NBH*SEQ];

// --------------------------- helpers ---------------------------------------
__device__ __forceinline__ u32 s2u(const void* p){
    u32 a; asm("{ .reg .u64 t; cvta.to.shared.u64 t, %1; cvt.u32.u64 %0, t; }":"=r"(a):"l"(p)); return a;
}
#define SWZ64(o) ((o) ^ (((o)>>3)&0x30))

__device__ __forceinline__ void cpa16(u32 d, const void* s){
    asm volatile("cp.async.cg.shared.global [%0], [%1], 16;" :: "r"(d), "l"(s));
}
__device__ __forceinline__ void cpc(){ asm volatile("cp.async.commit_group;"); }
template<int N> __device__ __forceinline__ void cpw(){ asm volatile("cp.async.wait_group %0;"::"n"(N)); }

__device__ __forceinline__ void ldm4(u32* r, u32 addr){
    asm volatile("ldmatrix.sync.aligned.m8n8.x4.shared.b16 {%0,%1,%2,%3}, [%4];"
        : "=r"(r[0]),"=r"(r[1]),"=r"(r[2]),"=r"(r[3]) : "r"(addr));
}
__device__ __forceinline__ void mma16816(float* d, const u32* a, u32 b0, u32 b1){
    asm volatile("mma.sync.aligned.m16n8k16.row.col.f32.bf16.bf16.f32 "
        "{%0,%1,%2,%3}, {%4,%5,%6,%7}, {%8,%9}, {%0,%1,%2,%3};"
        : "+f"(d[0]),"+f"(d[1]),"+f"(d[2]),"+f"(d[3])
        : "r"(a[0]),"r"(a[1]),"r"(a[2]),"r"(a[3]), "r"(b0),"r"(b1));
}
__device__ __forceinline__ void bsplit(float v, __nv_bfloat16& h, __nv_bfloat16& l){
    h = __float2bfloat16(v);
    l = __float2bfloat16(v - __bfloat162float(h));
}

// --------------------------- mma.sync GEMM ---------------------------------
// C[M,N] = alpha * sum_k A[m,k]*B[n,k] (row-major, k contiguous; "NT").
// A/B pre-split bf16 hi/lo; 3-term product (hh + hl + lh).
#define KC 32
#define TILE_B 8192               // 128 rows x 64B
#define STAGE_BYTES (4*TILE_B)    // 32KB
#define PIPE 3
#define GSMEM_SZ (1024 + PIPE*STAGE_BYTES)   // ~97KB -> 2 CTAs/SM

// EPI: 0 = f32 out, 1 = split bf16 hi/lo out, 2 = f32 scores + partial softmax
template<int EPI, int K, int LDA, int LDB, int LDC, int ZDIV,
         ll SAO, ll SAI, ll SBO, ll SBI, ll SCO, ll SCI>
__global__ __launch_bounds__(256, 2)
void gemm_mma(const __nv_bfloat16* __restrict__ Ahi, const __nv_bfloat16* __restrict__ Alo,
              const __nv_bfloat16* __restrict__ Bhi, const __nv_bfloat16* __restrict__ Blo,
              float* __restrict__ Cf, __nv_bfloat16* __restrict__ Chi, __nv_bfloat16* __restrict__ Clo,
              float* __restrict__ Pm, float* __restrict__ Ps, float alpha)
{
    extern __shared__ char smem[];
    const u32 stage0 = (s2u(smem) + 1023u) & ~1023u;
    const int tid = threadIdx.x;
    const int lane = tid & 31;
    const int wid = tid >> 5;
    const int wm = (wid & 1) * 64;          // 2 warp-rows of 64
    const int wn = (wid >> 1) * 32;         // 4 warp-cols of 32
    const int lrow16 = lane & 15;
    const int lcol16 = (lane >> 4) * 16;

    const int zo = blockIdx.z / ZDIV, zi = blockIdx.z % ZDIV;
    const ll aoff = zo*SAO + zi*SAI;
    const ll boff = zo*SBO + zi*SBI;
    const ll coff = zo*SCO + zi*SCI;

    const int m0 = blockIdx.y * 128;
    const int n0 = blockIdx.x * 128;
    const int NK = K / KC;

    // loader: 2 threads per row, 2x16B each; tile = 128 rows x 4 units
    const int arow = tid >> 1;
    const int aseg = (tid & 1) * 2;
    const __nv_bfloat16* pAh = Ahi + aoff + (ll)(m0 + arow)*LDA + aseg*8;
    const __nv_bfloat16* pAl = Alo + aoff + (ll)(m0 + arow)*LDA + aseg*8;
    const __nv_bfloat16* pBh = Bhi + boff + (ll)(n0 + arow)*LDB + aseg*8;
    const __nv_bfloat16* pBl = Blo + boff + (ll)(n0 + arow)*LDB + aseg*8;
    const u32 d0 = SWZ64((u32)(arow*64 + aseg*16));
    const u32 d1 = SWZ64((u32)(arow*64 + (aseg+1)*16));

    auto fetch = [&](int s){
        const u32 base = stage0 + (s % PIPE) * STAGE_BYTES;
        cpa16(base + d0,            pAh);     cpa16(base + d1,            pAh + 8);
        cpa16(base + TILE_B + d0,   pAl);     cpa16(base + TILE_B + d1,   pAl + 8);
        cpa16(base + 2*TILE_B + d0, pBh);     cpa16(base + 2*TILE_B + d1, pBh + 8);
        cpa16(base + 3*TILE_B + d0, pBl);     cpa16(base + 3*TILE_B + d1, pBl + 8);
        cpc();
        pAh += KC; pAl += KC; pBh += KC; pBl += KC;
    };

    float acc[4][4][4];
    #pragma unroll
    for (int i=0;i<4;i++)
    #pragma unroll
    for (int j=0;j<4;j++)
    #pragma unroll
    for (int r=0;r<4;r++) acc[i][j][r] = 0.f;

    int fetched = 0;
    for (; fetched < PIPE-1 && fetched < NK; fetched++) fetch(fetched);

    for (int kc = 0; kc < NK; kc++) {
        if (fetched < NK) { fetch(fetched); fetched++; }
        const int pend = fetched - kc - 1;
        if (pend <= 0) cpw<0>(); else if (pend == 1) cpw<1>(); else cpw<2>();
        __syncthreads();

        const u32 sb  = stage0 + (kc % PIPE) * STAGE_BYTES;
        const u32 sAh = sb, sAl = sb + TILE_B;
        const u32 sBh = sb + 2*TILE_B, sBl = sb + 3*TILE_B;

        #pragma unroll
        for (int k16 = 0; k16 < 2; k16++) {
            u32 a4[4][4];
            // pass 1: A-hi  x (B-hi, B-lo)
            #pragma unroll
            for (int mf = 0; mf < 4; mf++)
                ldm4(a4[mf], sAh + SWZ64((u32)((wm + mf*16 + lrow16)*64 + k16*32 + lcol16)));
            #pragma unroll
            for (int n2 = 0; n2 < 2; n2++) {
                u32 bh[4], bl[4];
                const u32 boffs = SWZ64((u32)((wn + n2*16 + lrow16)*64 + k16*32 + lcol16));
                ldm4(bh, sBh + boffs);
                ldm4(bl, sBl + boffs);
                #pragma unroll
                for (int od = 0; od < 2; od++) {
                    const int nf = n2*2 + od;
                    #pragma unroll
                    for (int mf = 0; mf < 4; mf++) {
                        mma16816(acc[mf][nf], a4[mf], bh[od], bh[od+2]);
                        mma16816(acc[mf][nf], a4[mf], bl[od], bl[od+2]);
                    }
                }
            }
            // pass 2: A-lo x B-hi  (reuse a4 registers)
            #pragma unroll
            for (int mf = 0; mf < 4; mf++)
                ldm4(a4[mf], sAl + SWZ64((u32)((wm + mf*16 + lrow16)*64 + k16*32 + lcol16)));
            #pragma unroll
            for (int n2 = 0; n2 < 2; n2++) {
                u32 bh[4];
                const u32 boffs = SWZ64((u32)((wn + n2*16 + lrow16)*64 + k16*32 + lcol16));
                ldm4(bh, sBh + boffs);
                #pragma unroll
                for (int od = 0; od < 2; od++) {
                    const int nf = n2*2 + od;
                    #pragma unroll
                    for (int mf = 0; mf < 4; mf++)
                        mma16816(acc[mf][nf], a4[mf], bh[od], bh[od+2]);
                }
            }
        }
        __syncthreads();
    }

    const int g = lane >> 2, tig = lane & 3;
    #pragma unroll
    for (int mf = 0; mf < 4; mf++) {
        #pragma unroll
        for (int nf = 0; nf < 4; nf++) {
            const ll m = m0 + wm + mf*16 + g;
            const int n = n0 + wn + nf*8 + tig*2;
            float v0 = acc[mf][nf][0]*alpha, v1 = acc[mf][nf][1]*alpha;
            float v2 = acc[mf][nf][2]*alpha, v3 = acc[mf][nf][3]*alpha;
            if (EPI != 1) {
                float2 v01 = {v0, v1}, v23 = {v2, v3};
                *reinterpret_cast<float2*>(Cf + coff + m*LDC + n) = v01;
                *reinterpret_cast<float2*>(Cf + coff + (m+8)*LDC + n) = v23;
            } else {
                __nv_bfloat16 h0,l0,h1,l1,h2,l2,h3,l3;
                bsplit(v0,h0,l0); bsplit(v1,h1,l1); bsplit(v2,h2,l2); bsplit(v3,h3,l3);
                __nv_bfloat162 hh01; hh01.x=h0; hh01.y=h1;
                __nv_bfloat162 ll01; ll01.x=l0; ll01.y=l1;
                __nv_bfloat162 hh23; hh23.x=h2; hh23.y=h3;
                __nv_bfloat162 ll23; ll23.x=l2; ll23.y=l3;
                *reinterpret_cast<u32*>(Chi + coff + m*LDC + n) = *reinterpret_cast<u32*>(&hh01);
                *reinterpret_cast<u32*>(Clo + coff + m*LDC + n) = *reinterpret_cast<u32*>(&ll01);
                *reinterpret_cast<u32*>(Chi + coff + (m+8)*LDC + n) = *reinterpret_cast<u32*>(&hh23);
                *reinterpret_cast<u32*>(Clo + coff + (m+8)*LDC + n) = *reinterpret_cast<u32*>(&ll23);
            }
        }
    }

    if (EPI == 2) {
        // partial softmax stats over this warp's 32 cols (stats already *alpha)
        const int bh = blockIdx.z;
        const int nt = (n0 + wn) >> 5;        // 0..63
        #pragma unroll
        for (int mf = 0; mf < 4; mf++) {
            #pragma unroll
            for (int half = 0; half < 2; half++) {
                const int r0i = half * 2;
                float mx = -1e30f;
                #pragma unroll
                for (int nf = 0; nf < 4; nf++)
                    mx = fmaxf(mx, fmaxf(acc[mf][nf][r0i], acc[mf][nf][r0i+1]));
                mx = fmaxf(mx, __shfl_xor_sync(0xffffffffu, mx, 1));
                mx = fmaxf(mx, __shfl_xor_sync(0xffffffffu, mx, 2));
                float sm = 0.f;
                #pragma unroll
                for (int nf = 0; nf < 4; nf++)
                    sm += __expf((acc[mf][nf][r0i] - mx)*alpha) + __expf((acc[mf][nf][r0i+1] - mx)*alpha);
                sm += __shfl_xor_sync(0xffffffffu, sm, 1);
                sm += __shfl_xor_sync(0xffffffffu, sm, 2);
                if (tig == 0) {
                    const int row = m0 + wm + mf*16 + g + half*8;
                    const ll idx = ((ll)bh*SEQ + row)*NTILES + nt;
                    Pm[idx] = mx*alpha; Ps[idx] = sm;
                }
            }
        }
    }
}

// --------------------------- prep kernels ----------------------------------
__global__ __launch_bounds__(256)
void split_x_kernel(const float* __restrict__ x, __nv_bfloat16* __restrict__ hi,
                    __nv_bfloat16* __restrict__ lo)
{
    const ll i = (ll)blockIdx.x * 256 + threadIdx.x;
    float v = x[i];
    __nv_bfloat16 h, l; bsplit(v, h, l);
    hi[i] = h; lo[i] = l;
}

// in [R,C] f32 -> out [C,R] split bf16
__global__ __launch_bounds__(256)
void transpose_split_kernel(const float* __restrict__ in, __nv_bfloat16* __restrict__ ohi,
                            __nv_bfloat16* __restrict__ olo, int R, int C)
{
    __shared__ float t[32][33];
    const int c0 = blockIdx.x * 32, r0 = blockIdx.y * 32;
    const int tx = threadIdx.x, ty = threadIdx.y;
    #pragma unroll
    for (int i = 0; i < 4; i++)
        t[ty + 8*i][tx] = in[(ll)(r0 + ty + 8*i) * C + c0 + tx];
    __syncthreads();
    #pragma unroll
    for (int i = 0; i < 4; i++) {
        float v = t[tx][ty + 8*i];
        __nv_bfloat16 h, l; bsplit(v, h, l);
        const ll o = (ll)(c0 + ty + 8*i) * R + r0 + tx;
        ohi[o] = h; olo[o] = l;
    }
}

// --------------------------- stats combine ---------------------------------
// one warp per row: combine 64 (pmax, psum) partials -> rowmax, rowinv
__global__ __launch_bounds__(256)
void stats_combine_kernel(const float* __restrict__ Pm, const float* __restrict__ Ps,
                          float* __restrict__ rowmax, float* __restrict__ rowinv)
{
    const int row = blockIdx.x * 8 + (threadIdx.x >> 5);
    const int lane = threadIdx.x & 31;
    float m1 = Pm[(ll)row*NTILES + lane];
    float m2 = Pm[(ll)row*NTILES + 32 + lane];
    float s1 = Ps[(ll)row*NTILES + lane];
    float s2 = Ps[(ll)row*NTILES + 32 + lane];
    float gm = fmaxf(m1, m2);
    #pragma unroll
    for (int o = 16; o; o >>= 1) gm = fmaxf(gm, __shfl_xor_sync(0xffffffffu, gm, o));
    float z = s1 * __expf(m1 - gm) + s2 * __expf(m2 - gm);
    #pragma unroll
    for (int o = 16; o; o >>= 1) z += __shfl_xor_sync(0xffffffffu, z, o);
    if (lane == 0) { rowmax[row] = gm; rowinv[row] = 1.0f / z; }
}

// colsum with q-split + atomics: grid (k_chunks, bh, q_chunks)
__global__ __launch_bounds__(256)
void colsum2_kernel(const float* __restrict__ S, const float* __restrict__ rowmax,
                    const float* __restrict__ rowinv, float* __restrict__ colsum)
{
    const int bh = blockIdx.y;
    const int k  = blockIdx.x * 256 + threadIdx.x;
    const int q0 = blockIdx.z * 128;
    const float* sp = S + (ll)bh*SEQ*SEQ + (ll)q0*SEQ + k;
    const float* mp = rowmax + bh*SEQ + q0;
    const float* ip = rowinv + bh*SEQ + q0;
    float acc = 0.f;
    #pragma unroll 4
    for (int q = 0; q < 128; q++)
        acc += __expf(sp[(ll)q*SEQ] - __ldg(&mp[q])) * __ldg(&ip[q]);
    atomicAdd(&colsum[bh*SEQ + k], acc);
}

// vals = v * colsum, re-split to bf16 hi/lo
__global__ __launch_bounds__(256)
void scale_v_split_kernel(const __nv_bfloat16* __restrict__ qhi, const __nv_bfloat16* __restrict__ qlo,
                          const float* __restrict__ colsum,
                          __nv_bfloat16* __restrict__ vhi, __nv_bfloat16* __restrict__ vlo)
{
    const ll idx = (ll)blockIdx.x * 256 + threadIdx.x;
    const int col = (int)(idx & (HDIM - 1));
    const int row = (int)(idx >> 11);
    const int h = col >> 7;
    const int b = row >> 11;
    const int s = row & (SEQ - 1);
    const ll qo = (ll)row * QN + 2*NH*DHEAD + col;
    float v = __bfloat162float(qhi[qo]) + __bfloat162float(qlo[qo]);
    v *= colsum[(b*NH + h)*SEQ + s];
    __nv_bfloat16 h16, l16; bsplit(v, h16, l16);
    vhi[idx] = h16; vlo[idx] = l16;
}

// ---------------------------------------------------------------------------
extern "C" void kernel_launch(void* const* d_in, const int* in_sizes, int n_in,
                              void* d_out, int out_size)
{
    const float* x     = (const float*)d_in[0];
    const float* w_qkv = (const float*)d_in[1];
    const float* w_o   = (const float*)d_in[2];
    float* out = (float*)d_out;

    __nv_bfloat16 *xhi,*xlo,*wqh,*wql,*woh,*wol,*qh,*qlp,*vh,*vl;
    float *scores,*rowmax,*rowinv,*colsum,*pmax,*psum;
    cudaGetSymbolAddress((void**)&xhi, g_xhi);   cudaGetSymbolAddress((void**)&xlo, g_xlo);
    cudaGetSymbolAddress((void**)&wqh, g_wqT_hi); cudaGetSymbolAddress((void**)&wql, g_wqT_lo);
    cudaGetSymbolAddress((void**)&woh, g_woT_hi); cudaGetSymbolAddress((void**)&wol, g_woT_lo);
    cudaGetSymbolAddress((void**)&qh,  g_qkv_hi); cudaGetSymbolAddress((void**)&qlp, g_qkv_lo);
    cudaGetSymbolAddress((void**)&vh,  g_vhi);    cudaGetSymbolAddress((void**)&vl,  g_vlo);
    cudaGetSymbolAddress((void**)&scores, g_scores);
    cudaGetSymbolAddress((void**)&rowmax, g_rowmax);
    cudaGetSymbolAddress((void**)&rowinv, g_rowinv);
    cudaGetSymbolAddress((void**)&colsum, g_colsum);
    cudaGetSymbolAddress((void**)&pmax, g_pmax);
    cudaGetSymbolAddress((void**)&psum, g_psum);

    auto k_qkv = gemm_mma<1, HDIM, HDIM, HDIM, QN, 1, 0,0,0,0,0,0>;
    auto k_sc  = gemm_mma<2, DHEAD, QN, QN, SEQ, NH,
                          (ll)SEQ*QN, 128, (ll)SEQ*QN, 128,
                          (ll)NH*SEQ*SEQ, (ll)SEQ*SEQ>;
    auto k_out = gemm_mma<0, HDIM, HDIM, HDIM, HDIM, 1, 0,0,0,0,0,0>;
    cudaFuncSetAttribute(k_qkv, cudaFuncAttributeMaxDynamicSharedMemorySize, GSMEM_SZ);
    cudaFuncSetAttribute(k_sc,  cudaFuncAttributeMaxDynamicSharedMemorySize, GSMEM_SZ);
    cudaFuncSetAttribute(k_out, cudaFuncAttributeMaxDynamicSharedMemorySize, GSMEM_SZ);

    // prep: split/transpose inputs
    split_x_kernel<<<(MR*HDIM)/256, 256>>>(x, xhi, xlo);
    transpose_split_kernel<<<dim3(QN/32, HDIM/32), dim3(32,8)>>>(w_qkv, wqh, wql, HDIM, QN);
    transpose_split_kernel<<<dim3(HDIM/32, HDIM/32), dim3(32,8)>>>(w_o, woh, wol, HDIM, HDIM);

    // 1) qkv = x @ w_qkv (split bf16 out)
    k_qkv<<<dim3(QN/128, MR/128, 1), 256, GSMEM_SZ>>>(
        xhi, xlo, wqh, wql, nullptr, qh, qlp, nullptr, nullptr, 1.0f);

    // 2) scores = (Q @ K^T)/sqrt(128) + partial softmax stats, z = b*16+h
    k_sc<<<dim3(SEQ/128, SEQ/128, NBH), 256, GSMEM_SZ>>>(
        qh, qlp, qh + NH*DHEAD, qlp + NH*DHEAD, scores, nullptr, nullptr,
        pmax, psum, 0.08838834764831845f);

    // 3) combine partial stats
    stats_combine_kernel<<<(NBH*SEQ)/8, 256>>>(pmax, psum, rowmax, rowinv);

    // 4) colsum over q (atomic, q-split)
    cudaMemsetAsync(colsum, 0, NBH*SEQ*sizeof(float));
    colsum2_kernel<<<dim3(SEQ/256, NBH, SEQ/128), 256>>>(scores, rowmax, rowinv, colsum);

    // 5) vals = v * colsum, split
    scale_v_split_kernel<<<(MR*HDIM)/256, 256>>>(qh, qlp, colsum, vh, vl);

    // 6) out = vals @ w_o
    k_out<<<dim3(HDIM/128, MR/128, 1), 256, GSMEM_SZ>>>(
        vh, vl, woh, wol, out, nullptr, nullptr, nullptr, nullptr, 1.0f);
}

// round 9
// speedup vs baseline: 1.6549x; 1.3453x over previous
#include <cuda_runtime.h>
#include <cuda_fp16.h>
#include <math.h>

// ---------------------------------------------------------------------------
// MegatronAttention B=2,S=2048,H=2048,NH=16,DH=128 — mma.sync fp16 2-term GEMMs
// D = (Ah+Al)*Bh, A split fp16 hi/lo, B rounded fp16 (err ~2.8e-4/GEMM).
// CTA 128x128, warp 64x32, KC=32 (SW64), PIPE=4, 2 CTAs/SM, 1 barrier/iter.
// out quirk: einsum 'bhqk,bhkd->bhkd' sums q -> out = v * colsum(softmax).
// (Resubmit of R7: prior bench hit "device busy" infra failure before launch.)
// ---------------------------------------------------------------------------
#define SEQ 2048
#define HDIM 2048
#define NH 16
#define DHEAD 128
#define MR 4096               // B*S
#define QN 6144               // 3*NH*DH
#define NBH 32
#define NTILES 64             // 2048/32 score col-tiles per row

typedef long long ll;
typedef unsigned int u32;

// --------------------------- scratch buffers -------------------------------
__device__ __half g_xhi[(size_t)MR*HDIM], g_xlo[(size_t)MR*HDIM];
__device__ __half g_wqT[(size_t)QN*HDIM];
__device__ __half g_woT[(size_t)HDIM*HDIM];
__device__ __half g_qkv_hi[(size_t)MR*QN], g_qkv_lo[(size_t)MR*QN];
__device__ float g_scores[(size_t)NBH*SEQ*SEQ];
__device__ __half g_vhi[(size_t)MR*HDIM], g_vlo[(size_t)MR*HDIM];
__device__ float g_pmax[(size_t)NBH*SEQ*NTILES], g_psum[(size_t)NBH*SEQ*NTILES];
__device__ float g_rowmax[NBH*SEQ], g_rowinv[NBH*SEQ], g_colsum[NBH*SEQ];

// --------------------------- helpers ---------------------------------------
__device__ __forceinline__ u32 s2u(const void* p){
    u32 a; asm("{ .reg .u64 t; cvta.to.shared.u64 t, %1; cvt.u32.u64 %0, t; }":"=r"(a):"l"(p)); return a;
}
#define SWZ64(o) ((o) ^ (((o)>>3)&0x30))

__device__ __forceinline__ void cpa16(u32 d, const void* s){
    asm volatile("cp.async.cg.shared.global [%0], [%1], 16;" :: "r"(d), "l"(s));
}
__device__ __forceinline__ void cpc(){ asm volatile("cp.async.commit_group;"); }
template<int N> __device__ __forceinline__ void cpw(){ asm volatile("cp.async.wait_group %0;"::"n"(N)); }

__device__ __forceinline__ void ldm4(u32* r, u32 addr){
    asm volatile("ldmatrix.sync.aligned.m8n8.x4.shared.b16 {%0,%1,%2,%3}, [%4];"
        : "=r"(r[0]),"=r"(r[1]),"=r"(r[2]),"=r"(r[3]) : "r"(addr));
}
__device__ __forceinline__ void mma16816(float* d, const u32* a, u32 b0, u32 b1){
    asm volatile("mma.sync.aligned.m16n8k16.row.col.f32.f16.f16.f32 "
        "{%0,%1,%2,%3}, {%4,%5,%6,%7}, {%8,%9}, {%0,%1,%2,%3};"
        : "+f"(d[0]),"+f"(d[1]),"+f"(d[2]),"+f"(d[3])
        : "r"(a[0]),"r"(a[1]),"r"(a[2]),"r"(a[3]), "r"(b0),"r"(b1));
}
__device__ __forceinline__ void hsplit(float v, __half& h, __half& l){
    h = __float2half(v);
    l = __float2half(v - __half2float(h));
}

// --------------------------- mma.sync GEMM ---------------------------------
// C[M,N] = alpha * sum_k A[m,k]*B[n,k] (row-major, k contiguous; "NT").
// A pre-split fp16 hi/lo; B fp16; 2-term product (Ah+Al)*B.
#define KC 32
#define TILE_B 8192               // 128 rows x 64B
#define STAGE_BYTES (3*TILE_B)    // Ah, Al, Bh = 24KB
#define PIPE 4
#define GSMEM_SZ (1024 + PIPE*STAGE_BYTES)   // ~97KB -> 2 CTAs/SM

// EPI: 0 = f32 out, 1 = split fp16 hi/lo out, 2 = f32 scores + partial softmax
template<int EPI, int K, int LDA, int LDB, int LDC, int ZDIV,
         ll SAO, ll SAI, ll SBO, ll SBI, ll SCO, ll SCI>
__global__ __launch_bounds__(256, 2)
void gemm_mma(const __half* __restrict__ Ahi, const __half* __restrict__ Alo,
              const __half* __restrict__ Bh,
              float* __restrict__ Cf, __half* __restrict__ Chi, __half* __restrict__ Clo,
              float* __restrict__ Pm, float* __restrict__ Ps, float alpha)
{
    extern __shared__ char smem[];
    const u32 stage0 = (s2u(smem) + 1023u) & ~1023u;
    const int tid = threadIdx.x;
    const int lane = tid & 31;
    const int wid = tid >> 5;
    const int wm = (wid & 1) * 64;
    const int wn = (wid >> 1) * 32;
    const int lrow16 = lane & 15;
    const int lcol16 = (lane >> 4) * 16;

    const int zo = blockIdx.z / ZDIV, zi = blockIdx.z % ZDIV;
    const ll aoff = zo*SAO + zi*SAI;
    const ll boff = zo*SBO + zi*SBI;
    const ll coff = zo*SCO + zi*SCI;

    const int m0 = blockIdx.y * 128;
    const int n0 = blockIdx.x * 128;
    const int NK = K / KC;

    // loader: 2 threads per row, 2x16B each; tile = 128 rows x 64B
    const int arow = tid >> 1;
    const int aseg = (tid & 1) * 2;
    const __half* pAh = Ahi + aoff + (ll)(m0 + arow)*LDA + aseg*8;
    const __half* pAl = Alo + aoff + (ll)(m0 + arow)*LDA + aseg*8;
    const __half* pBh = Bh  + boff + (ll)(n0 + arow)*LDB + aseg*8;
    const u32 d0 = SWZ64((u32)(arow*64 + aseg*16));
    const u32 d1 = SWZ64((u32)(arow*64 + (aseg+1)*16));

    auto fetch = [&](int s){
        const u32 base = stage0 + (s % PIPE) * STAGE_BYTES;
        cpa16(base + d0,            pAh);  cpa16(base + d1,            pAh + 8);
        cpa16(base + TILE_B + d0,   pAl);  cpa16(base + TILE_B + d1,   pAl + 8);
        cpa16(base + 2*TILE_B + d0, pBh);  cpa16(base + 2*TILE_B + d1, pBh + 8);
        cpc();
        pAh += KC; pAl += KC; pBh += KC;
    };

    float acc[4][4][4];
    #pragma unroll
    for (int i=0;i<4;i++)
    #pragma unroll
    for (int j=0;j<4;j++)
    #pragma unroll
    for (int r=0;r<4;r++) acc[i][j][r] = 0.f;

    int fetched = 0;
    for (; fetched < PIPE-1 && fetched < NK; fetched++) fetch(fetched);

    for (int kc = 0; kc < NK; kc++) {
        const int pend = fetched - kc - 1;
        if (pend <= 0) cpw<0>(); else if (pend == 1) cpw<1>(); else cpw<2>();
        __syncthreads();
        if (fetched < NK) { fetch(fetched); fetched++; }

        const u32 sb  = stage0 + (kc % PIPE) * STAGE_BYTES;
        const u32 sAh = sb, sAl = sb + TILE_B, sBh = sb + 2*TILE_B;

        #pragma unroll
        for (int k16 = 0; k16 < 2; k16++) {
            u32 a4[4][4], bh[2][4];
            // B frags loaded once, live across both A passes
            #pragma unroll
            for (int n2 = 0; n2 < 2; n2++)
                ldm4(bh[n2], sBh + SWZ64((u32)((wn + n2*16 + lrow16)*64 + k16*32 + lcol16)));
            // pass 1: A-hi x B
            #pragma unroll
            for (int mf = 0; mf < 4; mf++)
                ldm4(a4[mf], sAh + SWZ64((u32)((wm + mf*16 + lrow16)*64 + k16*32 + lcol16)));
            #pragma unroll
            for (int n2 = 0; n2 < 2; n2++)
            #pragma unroll
            for (int od = 0; od < 2; od++) {
                const int nf = n2*2 + od;
                #pragma unroll
                for (int mf = 0; mf < 4; mf++)
                    mma16816(acc[mf][nf], a4[mf], bh[n2][od], bh[n2][od+2]);
            }
            // pass 2: A-lo x B (reuse a4 regs)
            #pragma unroll
            for (int mf = 0; mf < 4; mf++)
                ldm4(a4[mf], sAl + SWZ64((u32)((wm + mf*16 + lrow16)*64 + k16*32 + lcol16)));
            #pragma unroll
            for (int n2 = 0; n2 < 2; n2++)
            #pragma unroll
            for (int od = 0; od < 2; od++) {
                const int nf = n2*2 + od;
                #pragma unroll
                for (int mf = 0; mf < 4; mf++)
                    mma16816(acc[mf][nf], a4[mf], bh[n2][od], bh[n2][od+2]);
            }
        }
    }

    const int g = lane >> 2, tig = lane & 3;
    #pragma unroll
    for (int mf = 0; mf < 4; mf++) {
        #pragma unroll
        for (int nf = 0; nf < 4; nf++) {
            const ll m = m0 + wm + mf*16 + g;
            const int n = n0 + wn + nf*8 + tig*2;
            float v0 = acc[mf][nf][0]*alpha, v1 = acc[mf][nf][1]*alpha;
            float v2 = acc[mf][nf][2]*alpha, v3 = acc[mf][nf][3]*alpha;
            if (EPI != 1) {
                float2 v01 = {v0, v1}, v23 = {v2, v3};
                *reinterpret_cast<float2*>(Cf + coff + m*LDC + n) = v01;
                *reinterpret_cast<float2*>(Cf + coff + (m+8)*LDC + n) = v23;
            } else {
                __half h0,l0,h1,l1,h2,l2,h3,l3;
                hsplit(v0,h0,l0); hsplit(v1,h1,l1); hsplit(v2,h2,l2); hsplit(v3,h3,l3);
                __half2 hh01 = __halves2half2(h0,h1), ll01 = __halves2half2(l0,l1);
                __half2 hh23 = __halves2half2(h2,h3), ll23 = __halves2half2(l2,l3);
                *reinterpret_cast<u32*>(Chi + coff + m*LDC + n) = *reinterpret_cast<u32*>(&hh01);
                *reinterpret_cast<u32*>(Clo + coff + m*LDC + n) = *reinterpret_cast<u32*>(&ll01);
                *reinterpret_cast<u32*>(Chi + coff + (m+8)*LDC + n) = *reinterpret_cast<u32*>(&hh23);
                *reinterpret_cast<u32*>(Clo + coff + (m+8)*LDC + n) = *reinterpret_cast<u32*>(&ll23);
            }
        }
    }

    if (EPI == 2) {
        // partial softmax stats over this warp's 32 cols
        const int bh_ = blockIdx.z;
        const int nt = (n0 + wn) >> 5;
        #pragma unroll
        for (int mf = 0; mf < 4; mf++) {
            #pragma unroll
            for (int half = 0; half < 2; half++) {
                const int r0i = half * 2;
                float mx = -1e30f;
                #pragma unroll
                for (int nf = 0; nf < 4; nf++)
                    mx = fmaxf(mx, fmaxf(acc[mf][nf][r0i], acc[mf][nf][r0i+1]));
                mx = fmaxf(mx, __shfl_xor_sync(0xffffffffu, mx, 1));
                mx = fmaxf(mx, __shfl_xor_sync(0xffffffffu, mx, 2));
                float sm = 0.f;
                #pragma unroll
                for (int nf = 0; nf < 4; nf++)
                    sm += __expf((acc[mf][nf][r0i] - mx)*alpha) + __expf((acc[mf][nf][r0i+1] - mx)*alpha);
                sm += __shfl_xor_sync(0xffffffffu, sm, 1);
                sm += __shfl_xor_sync(0xffffffffu, sm, 2);
                if (tig == 0) {
                    const int row = m0 + wm + mf*16 + g + half*8;
                    const ll idx = ((ll)bh_*SEQ + row)*NTILES + nt;
                    Pm[idx] = mx*alpha; Ps[idx] = sm;
                }
            }
        }
    }
}

// --------------------------- prep kernels ----------------------------------
__global__ __launch_bounds__(256)
void split_x_kernel(const float* __restrict__ x, __half* __restrict__ hi,
                    __half* __restrict__ lo)
{
    const ll i = (ll)blockIdx.x * 256 + threadIdx.x;
    float v = x[i];
    __half h, l; hsplit(v, h, l);
    hi[i] = h; lo[i] = l;
}

// in [R,C] f32 -> out [C,R] fp16 (rounded)
__global__ __launch_bounds__(256)
void transpose_round_kernel(const float* __restrict__ in, __half* __restrict__ o16,
                            int R, int C)
{
    __shared__ float t[32][33];
    const int c0 = blockIdx.x * 32, r0 = blockIdx.y * 32;
    const int tx = threadIdx.x, ty = threadIdx.y;
    #pragma unroll
    for (int i = 0; i < 4; i++)
        t[ty + 8*i][tx] = in[(ll)(r0 + ty + 8*i) * C + c0 + tx];
    __syncthreads();
    #pragma unroll
    for (int i = 0; i < 4; i++) {
        const ll o = (ll)(c0 + ty + 8*i) * R + r0 + tx;
        o16[o] = __float2half(t[tx][ty + 8*i]);
    }
}

// --------------------------- stats combine ---------------------------------
// one warp per row: combine 64 (pmax, psum) partials -> rowmax, rowinv
__global__ __launch_bounds__(256)
void stats_combine_kernel(const float* __restrict__ Pm, const float* __restrict__ Ps,
                          float* __restrict__ rowmax, float* __restrict__ rowinv)
{
    const int row = blockIdx.x * 8 + (threadIdx.x >> 5);
    const int lane = threadIdx.x & 31;
    float m1 = Pm[(ll)row*NTILES + lane];
    float m2 = Pm[(ll)row*NTILES + 32 + lane];
    float s1 = Ps[(ll)row*NTILES + lane];
    float s2 = Ps[(ll)row*NTILES + 32 + lane];
    float gm = fmaxf(m1, m2);
    #pragma unroll
    for (int o = 16; o; o >>= 1) gm = fmaxf(gm, __shfl_xor_sync(0xffffffffu, gm, o));
    float z = s1 * __expf(m1 - gm) + s2 * __expf(m2 - gm);
    #pragma unroll
    for (int o = 16; o; o >>= 1) z += __shfl_xor_sync(0xffffffffu, z, o);
    if (lane == 0) { rowmax[row] = gm; rowinv[row] = 1.0f / z; }
}

// colsum with q-split + atomics: grid (k_chunks, bh, q_chunks)
__global__ __launch_bounds__(256)
void colsum2_kernel(const float* __restrict__ S, const float* __restrict__ rowmax,
                    const float* __restrict__ rowinv, float* __restrict__ colsum)
{
    const int bh = blockIdx.y;
    const int k  = blockIdx.x * 256 + threadIdx.x;
    const int q0 = blockIdx.z * 128;
    const float* sp = S + (ll)bh*SEQ*SEQ + (ll)q0*SEQ + k;
    const float* mp = rowmax + bh*SEQ + q0;
    const float* ip = rowinv + bh*SEQ + q0;
    float acc = 0.f;
    #pragma unroll 4
    for (int q = 0; q < 128; q++)
        acc += __expf(sp[(ll)q*SEQ] - __ldg(&mp[q])) * __ldg(&ip[q]);
    atomicAdd(&colsum[bh*SEQ + k], acc);
}

// vals = v * colsum, re-split to fp16 hi/lo
__global__ __launch_bounds__(256)
void scale_v_split_kernel(const __half* __restrict__ qhi, const __half* __restrict__ qlo,
                          const float* __restrict__ colsum,
                          __half* __restrict__ vhi, __half* __restrict__ vlo)
{
    const ll idx = (ll)blockIdx.x * 256 + threadIdx.x;
    const int col = (int)(idx & (HDIM - 1));
    const int row = (int)(idx >> 11);
    const int h = col >> 7;
    const int b = row >> 11;
    const int s = row & (SEQ - 1);
    const ll qo = (ll)row * QN + 2*NH*DHEAD + col;
    float v = __half2float(qhi[qo]) + __half2float(qlo[qo]);
    v *= colsum[(b*NH + h)*SEQ + s];
    __half h16, l16; hsplit(v, h16, l16);
    vhi[idx] = h16; vlo[idx] = l16;
}

// ---------------------------------------------------------------------------
extern "C" void kernel_launch(void* const* d_in, const int* in_sizes, int n_in,
                              void* d_out, int out_size)
{
    const float* x     = (const float*)d_in[0];
    const float* w_qkv = (const float*)d_in[1];
    const float* w_o   = (const float*)d_in[2];
    float* out = (float*)d_out;

    __half *xhi,*xlo,*wq,*wo,*qh,*qlp,*vh,*vl;
    float *scores,*rowmax,*rowinv,*colsum,*pmax,*psum;
    cudaGetSymbolAddress((void**)&xhi, g_xhi);   cudaGetSymbolAddress((void**)&xlo, g_xlo);
    cudaGetSymbolAddress((void**)&wq,  g_wqT);   cudaGetSymbolAddress((void**)&wo,  g_woT);
    cudaGetSymbolAddress((void**)&qh,  g_qkv_hi); cudaGetSymbolAddress((void**)&qlp, g_qkv_lo);
    cudaGetSymbolAddress((void**)&vh,  g_vhi);    cudaGetSymbolAddress((void**)&vl,  g_vlo);
    cudaGetSymbolAddress((void**)&scores, g_scores);
    cudaGetSymbolAddress((void**)&rowmax, g_rowmax);
    cudaGetSymbolAddress((void**)&rowinv, g_rowinv);
    cudaGetSymbolAddress((void**)&colsum, g_colsum);
    cudaGetSymbolAddress((void**)&pmax, g_pmax);
    cudaGetSymbolAddress((void**)&psum, g_psum);

    auto k_qkv = gemm_mma<1, HDIM, HDIM, HDIM, QN, 1, 0,0,0,0,0,0>;
    auto k_sc  = gemm_mma<2, DHEAD, QN, QN, SEQ, NH,
                          (ll)SEQ*QN, 128, (ll)SEQ*QN, 128,
                          (ll)NH*SEQ*SEQ, (ll)SEQ*SEQ>;
    auto k_out = gemm_mma<0, HDIM, HDIM, HDIM, HDIM, 1, 0,0,0,0,0,0>;
    cudaFuncSetAttribute(k_qkv, cudaFuncAttributeMaxDynamicSharedMemorySize, GSMEM_SZ);
    cudaFuncSetAttribute(k_sc,  cudaFuncAttributeMaxDynamicSharedMemorySize, GSMEM_SZ);
    cudaFuncSetAttribute(k_out, cudaFuncAttributeMaxDynamicSharedMemorySize, GSMEM_SZ);

    // prep: split x, round+transpose weights
    split_x_kernel<<<(MR*HDIM)/256, 256>>>(x, xhi, xlo);
    transpose_round_kernel<<<dim3(QN/32, HDIM/32), dim3(32,8)>>>(w_qkv, wq, HDIM, QN);
    transpose_round_kernel<<<dim3(HDIM/32, HDIM/32), dim3(32,8)>>>(w_o, wo, HDIM, HDIM);

    // 1) qkv = x @ w_qkv (split fp16 out)
    k_qkv<<<dim3(QN/128, MR/128, 1), 256, GSMEM_SZ>>>(
        xhi, xlo, wq, nullptr, qh, qlp, nullptr, nullptr, 1.0f);

    // 2) scores = (Q @ K^T)/sqrt(128) + partial softmax stats, z = b*16+h
    //    A = Q split (hi/lo), B = K-hi (fp16 round of k)
    k_sc<<<dim3(SEQ/128, SEQ/128, NBH), 256, GSMEM_SZ>>>(
        qh, qlp, qh + NH*DHEAD, scores, nullptr, nullptr,
        pmax, psum, 0.08838834764831845f);

    // 3) combine partial stats
    stats_combine_kernel<<<(NBH*SEQ)/8, 256>>>(pmax, psum, rowmax, rowinv);

    // 4) colsum over q (atomic, q-split)
    cudaMemsetAsync(colsum, 0, NBH*SEQ*sizeof(float));
    colsum2_kernel<<<dim3(SEQ/256, NBH, SEQ/128), 256>>>(scores, rowmax, rowinv, colsum);

    // 5) vals = v * colsum, split fp16
    scale_v_split_kernel<<<(MR*HDIM)/256, 256>>>(qh, qlp, colsum, vh, vl);

    // 6) out = vals @ w_o
    k_out<<<dim3(HDIM/128, MR/128, 1), 256, GSMEM_SZ>>>(
        vh, vl, wo, out, nullptr, nullptr, nullptr, nullptr, 1.0f);
}